// round 8
// baseline (speedup 1.0000x reference)
#include <cuda_runtime.h>

// Problem constants
#define BB    8
#define CCH   96          // channels
#define TT    1000
#define FF    64
#define LL    12          // layers
#define NCOL  512         // B*F columns
#define PP    12          // parts (CTAs) per layer
#define NT    384         // threads per CTA
#define DD    4           // state ring depth
#define WW    48          // padded cols per CTA (max M = 43)
#define WH    50          // cols + 2 halo
#define EPSF  1e-6f

// ---------------- device globals (no runtime alloc) ------------------------
__device__ float g_hbuf[LL * DD * CCH * NCOL];   // state/output ring
__device__ float g_rs  [LL * DD * NCOL];         // published rms stats ring
__device__ float g_xwT [LL * CCH * 288];         // xproj^T * inw   [l][k][o]
__device__ float g_pwT [LL * CCH * 288];         // hproj^T * hnw   [l][k][o]
__device__ float g_pbF [LL * 288];               // pb + pw . hb
__device__ int   g_prog[LL * PP];                // per-(layer,part) steps done

// smem layout (floats)
#define OFF_Y    0                     // raw y                96*48
#define OFF_HP   4608                  // hp with halo         96*50
#define OFF_HC   9408                  // conv out / s-buffer  96*48
#define OFF_RY   14016                 // rms of y cols        48
#define OFF_RH   14064                 // rms of hp cols       52 (padded)
#define OFF_RO   14116                 // rms of s cols        48
#define OFF_ONW  14164                 // 96
#define OFF_XB   14260                 // 288
#define OFF_PB   14548                 // 288 (folded)
#define OFF_HW   14836                 // 3*96 taps [d][c]
#define SMEM_FLOATS 15124
#define SMEM_BYTES  (SMEM_FLOATS * 4)

typedef unsigned long long u64;

__device__ __forceinline__ u64 fma2(u64 a, u64 b, u64 c) {
    u64 d;
    asm("fma.rn.f32x2 %0, %1, %2, %3;" : "=l"(d) : "l"(a), "l"(b), "l"(c));
    return d;
}
__device__ __forceinline__ u64 pack2(float x) {
    u64 d; asm("mov.b64 %0, {%1, %1};" : "=l"(d) : "f"(x)); return d;
}
__device__ __forceinline__ float2 unpack2(u64 v) {
    float2 r; asm("mov.b64 {%0, %1}, %2;" : "=f"(r.x), "=f"(r.y) : "l"(v)); return r;
}
__device__ __forceinline__ int ld_vol(const int* p) {
    int v;
    asm volatile("ld.volatile.global.b32 %0, [%1];" : "=r"(v) : "l"(p) : "memory");
    return v;
}
__device__ __forceinline__ void st_vol(int* p, int v) {
    asm volatile("st.volatile.global.b32 [%0], %1;" :: "l"(p), "r"(v) : "memory");
}
__device__ __forceinline__ void spin_ge(const int* p, int tgt) {
    while (ld_vol(p) < tgt) {
#if __CUDA_ARCH__ >= 700
        __nanosleep(32);
#endif
    }
}
__device__ __forceinline__ float fsigm(float x) {   // overflow-safe
    return __fdividef(1.f, 1.f + __expf(-x));
}
__device__ __forceinline__ float ftanh(float x) {   // overflow-safe
    float e = __expf(2.f * x);
    return 1.f - __fdividef(2.f, 1.f + e);
}

// ---------------- init: flags, ring zeros, weight folding ------------------
__global__ void gru_init(const float* __restrict__ xw, const float* __restrict__ pw,
                         const float* __restrict__ inw, const float* __restrict__ hnw,
                         const float* __restrict__ hb,  const float* __restrict__ pb) {
    int idx = blockIdx.x * blockDim.x + threadIdx.x;
    int stride = gridDim.x * blockDim.x;
    for (int i = idx; i < LL * PP; i += stride) g_prog[i] = 0;
    const int SLOT = CCH * NCOL;
    for (int i = idx; i < LL * SLOT; i += stride) {
        int l = i / SLOT, r = i - l * SLOT;
        g_hbuf[(l * DD + (DD - 1)) * SLOT + r] = 0.f;     // h at t=-1 is zero
    }
    for (int i = idx; i < LL * DD * NCOL; i += stride) g_rs[i] = 0.f;
    const int WSZ = 288 * CCH;
    for (int i = idx; i < LL * WSZ; i += stride) {
        int l = i / WSZ, r = i - l * WSZ;
        int o = r / CCH, ci = r - o * CCH;
        g_xwT[l * WSZ + ci * 288 + o] = xw[i] * inw[l * CCH + ci];
        g_pwT[l * WSZ + ci * 288 + o] = pw[i] * hnw[l * CCH + ci];
    }
    for (int i = idx; i < LL * 288; i += stride) {
        int l = i / 288, o = i - l * 288;
        float s = pb[i];
        for (int k = 0; k < CCH; ++k) s += pw[(l * 288 + o) * CCH + k] * hb[l * CCH + k];
        g_pbF[i] = s;
    }
}

// ---------------- main persistent wavefront kernel -------------------------
__global__ void __launch_bounds__(NT, 1) gru_main(
    const float* __restrict__ x,
    const float* __restrict__ xpb_g,
    const float* __restrict__ hw_g,
    const float* __restrict__ onw_g,
    float* __restrict__ out)
{
    extern __shared__ float sm[];
    const int tid  = threadIdx.x;
    const int l    = blockIdx.x / PP;
    const int part = blockIdx.x % PP;
    const int n0 = (part * NCOL) / PP;
    const int n1 = ((part + 1) * NCOL) / PP;
    const int M  = n1 - n0;                    // 42 or 43

    // layer params -> smem (persist); init HP/RH to finite zeros
    for (int i = tid; i < CCH; i += NT) {
        sm[OFF_ONW + i]      = onw_g[l * CCH + i];
        sm[OFF_HW       + i] = hw_g[(l * CCH + i) * 3 + 0];
        sm[OFF_HW +  96 + i] = hw_g[(l * CCH + i) * 3 + 1];
        sm[OFF_HW + 192 + i] = hw_g[(l * CCH + i) * 3 + 2];
    }
    for (int i = tid; i < 288; i += NT) {
        sm[OFF_XB + i] = xpb_g[l * 288 + i];
        sm[OFF_PB + i] = g_pbF[l * 288 + i];
    }
    for (int i = tid; i < CCH * WH; i += NT) sm[OFF_HP + i] = 0.f;
    for (int i = tid; i < 52; i += NT)       sm[OFF_RH + i] = 0.f;
    __syncthreads();

    const int SLOT = CCH * NCOL;
    const float* __restrict__ xwT = g_xwT + l * (CCH * 288);
    const float* __restrict__ pwT = g_pwT + l * (CCH * 288);
    float* hbl = g_hbuf + l * (DD * SLOT);
    float* rsl = g_rs   + l * (DD * NCOL);

    const int c  = tid % CCH;        // channel lane
    const int q  = tid / CCH;        // column group
    const int mb = q * 12;
    const float xb0 = sm[OFF_XB + c], xb1 = sm[OFF_XB + 96 + c], xb2 = sm[OFF_XB + 192 + c];
    const float pb0 = sm[OFF_PB + c], pb1 = sm[OFF_PB + 96 + c], pb2 = sm[OFF_PB + 192 + c];

    #pragma unroll 1
    for (int t = 0; t < TT; ++t) {
        // ---- layer 0: x is a pure input, load BEFORE the spin ----
        if (l == 0) {
            for (int idx = tid; idx < CCH * WW; idx += NT) {
                int cc = idx / WW, m = idx - cc * WW;
                float v = 0.f;
                if (m < M) {
                    int n = n0 + m;
                    v = x[(((n >> 6) * CCH + cc) * TT + t) * FF + (n & 63)];
                }
                sm[OFF_Y + idx] = v;
            }
        }

        // ---- fine-grained dependency spin (tid 0; <=4 flags) ----
        if (tid == 0) {
            if (part > 0)      spin_ge(&g_prog[l * PP + part - 1], t);
            if (part < PP - 1) spin_ge(&g_prog[l * PP + part + 1], t);
            if (l > 0)         spin_ge(&g_prog[(l - 1) * PP + part], t + 1);
            if (l < LL - 1 && t >= DD - 1)
                               spin_ge(&g_prog[(l + 1) * PP + part], t - DD + 1);
            __threadfence();   // invalidate L1 before this step's global reads
        }
        __syncthreads();

        const float* hprev = hbl + ((t + DD - 1) % DD) * SLOT;

        // ---- Phase A: y (l>0), hp halo (2 cols), forwarded stats ----
        if (l > 0) {
            const float* ysrc = g_hbuf + ((l - 1) * DD + (t % DD)) * SLOT;
            for (int idx = tid; idx < CCH * WW; idx += NT) {
                int cc = idx / WW, m = idx - cc * WW;
                sm[OFF_Y + idx] = (m < M) ? ysrc[cc * NCOL + n0 + m] : 0.f;
            }
            const float* rsy = g_rs + ((l - 1) * DD + (t % DD)) * NCOL;
            if (tid < WW) sm[OFF_RY + tid] = (tid < M) ? rsy[n0 + tid] : 0.f;
        }
        if (tid < 2 * CCH) {
            int side = tid / CCH, cc = tid - side * CCH;
            int n = side ? n1 : (n0 - 1);
            int j = side ? (M + 1) : 0;
            sm[OFF_HP + cc * WH + j] = (n >= 0 && n < NCOL) ? hprev[cc * NCOL + n] : 0.f;
        }
        {
            const float* rsh = rsl + ((t + DD - 1) % DD) * NCOL;
            if (tid == NT - 1) { int n = n0 - 1; sm[OFF_RH + 0]     = (n >= 0)   ? rsh[n] : 0.f; }
            if (tid == NT - 2) { int n = n1;     sm[OFF_RH + M + 1] = (n < NCOL) ? rsh[n] : 0.f; }
        }
        __syncthreads();

        // ---- layer 0 only: local RY reduction (8 threads / column) ----
        if (l == 0) {
            int col = tid >> 3, sub = tid & 7;
            float s1 = 0.f;
            #pragma unroll
            for (int i = 0; i < 12; ++i) {
                float a = sm[OFF_Y + (sub + 8 * i) * WW + col];
                s1 += a * a;
            }
            s1 += __shfl_xor_sync(0xffffffffu, s1, 1);
            s1 += __shfl_xor_sync(0xffffffffu, s1, 2);
            s1 += __shfl_xor_sync(0xffffffffu, s1, 4);
            if (sub == 0) sm[OFF_RY + col] = rsqrtf(s1 * (1.f / 96.f) + EPSF);
            __syncthreads();
        }

        // ---- Phase B: hc = conv(hp * RH) (norm weights folded into pwT) ----
        for (int idx = tid; idx < CCH * WW; idx += NT) {
            int cc = idx / WW, m = idx - cc * WW;
            float hc = 0.f;
            if (m < M) {
                int f = (n0 + m) & 63;
                float acc = sm[OFF_HP + cc * WH + m + 1] * sm[OFF_RH + m + 1] * sm[OFF_HW + 96 + cc];
                if (f != 0)  acc += sm[OFF_HP + cc * WH + m]     * sm[OFF_RH + m]     * sm[OFF_HW + cc];
                if (f != 63) acc += sm[OFF_HP + cc * WH + m + 2] * sm[OFF_RH + m + 2] * sm[OFF_HW + 192 + cc];
                hc = acc;
            }
            sm[OFF_HC + idx] = hc;
        }
        __syncthreads();

        // ---- Phase C: fused dual GEMM on RAW y + hc, f32x2 packed ----
        u64 aXr[6], aXz[6], aXn[6], aHr[6], aHz[6], aHn[6];
        #pragma unroll
        for (int j = 0; j < 6; ++j) { aXr[j]=0ULL; aXz[j]=0ULL; aXn[j]=0ULL; aHr[j]=0ULL; aHz[j]=0ULL; aHn[j]=0ULL; }

        #pragma unroll 2
        for (int k = 0; k < CCH; ++k) {
            const u64 Wx0 = pack2(__ldg(xwT + k * 288 + c));
            const u64 Wx1 = pack2(__ldg(xwT + k * 288 + 96 + c));
            const u64 Wx2 = pack2(__ldg(xwT + k * 288 + 192 + c));
            const u64 Wp0 = pack2(__ldg(pwT + k * 288 + c));
            const u64 Wp1 = pack2(__ldg(pwT + k * 288 + 96 + c));
            const u64 Wp2 = pack2(__ldg(pwT + k * 288 + 192 + c));
            const u64* ynp = (const u64*)(sm + OFF_Y  + k * WW + mb);
            const u64* hcp = (const u64*)(sm + OFF_HC + k * WW + mb);
            #pragma unroll
            for (int j = 0; j < 6; ++j) {
                u64 yv = ynp[j], hv = hcp[j];
                aXr[j] = fma2(Wx0, yv, aXr[j]);
                aXz[j] = fma2(Wx1, yv, aXz[j]);
                aXn[j] = fma2(Wx2, yv, aXn[j]);
                aHr[j] = fma2(Wp0, hv, aHr[j]);
                aHz[j] = fma2(Wp1, hv, aHz[j]);
                aHn[j] = fma2(Wp2, hv, aHn[j]);
            }
        }

        // ---- Phase D: gates (RY applied post-GEMM), s = h_new + y ----
        float sv[12];
        #pragma unroll
        for (int jj = 0; jj < 6; ++jj) {
            float2 xr2 = unpack2(aXr[jj]), xz2 = unpack2(aXz[jj]), xn2 = unpack2(aXn[jj]);
            float2 hr2 = unpack2(aHr[jj]), hz2 = unpack2(aHz[jj]), hn2 = unpack2(aHn[jj]);
            #pragma unroll
            for (int s2 = 0; s2 < 2; ++s2) {
                int m = mb + 2 * jj + s2;
                float ry = sm[OFF_RY + m];
                float xr = ry * (s2 ? xr2.y : xr2.x) + xb0;
                float xz = ry * (s2 ? xz2.y : xz2.x) + xb1;
                float xn = ry * (s2 ? xn2.y : xn2.x) + xb2;
                float hr = (s2 ? hr2.y : hr2.x) + pb0;
                float hz = (s2 ? hz2.y : hz2.x) + pb1;
                float hn = (s2 ? hn2.y : hn2.x) + pb2;
                float r = fsigm(xr + hr);
                float z = fsigm(xz + hz);
                float cand = ftanh(xn + r * hn);
                float hp = sm[OFF_HP + c * WH + m + 1];
                float hnew = (1.f - z) * cand + z * hp;
                float s = hnew + sm[OFF_Y + c * WW + m];
                sv[2 * jj + s2] = (m < M) ? s : 0.f;
            }
        }
        __syncthreads();  // GEMM reads of HC complete; reuse HC as s-buffer
        {
            float4* sp = (float4*)(sm + OFF_HC + c * WW + mb);
            sp[0] = make_float4(sv[0], sv[1], sv[2],  sv[3]);
            sp[1] = make_float4(sv[4], sv[5], sv[6],  sv[7]);
            sp[2] = make_float4(sv[8], sv[9], sv[10], sv[11]);
        }
        __syncthreads();

        // ---- out RMS + published stat, 8 threads/col, dual accumulators ----
        {
            int col = tid >> 3, sub = tid & 7;
            float s1 = 0.f, s2a = 0.f;
            #pragma unroll
            for (int i = 0; i < 12; ++i) {
                int c2 = sub + 8 * i;
                float a = sm[OFF_HC + c2 * WW + col];
                float aw = a * sm[OFF_ONW + c2];
                s1 += a * a;
                s2a += aw * aw;
            }
            s1  += __shfl_xor_sync(0xffffffffu, s1, 1);
            s2a += __shfl_xor_sync(0xffffffffu, s2a, 1);
            s1  += __shfl_xor_sync(0xffffffffu, s1, 2);
            s2a += __shfl_xor_sync(0xffffffffu, s2a, 2);
            s1  += __shfl_xor_sync(0xffffffffu, s1, 4);
            s2a += __shfl_xor_sync(0xffffffffu, s2a, 4);
            if (sub == 0) {
                float ro = rsqrtf(s1 * (1.f / 96.f) + EPSF);
                sm[OFF_RO + col] = ro;
                if (col < M) {
                    float rp = rsqrtf(ro * ro * s2a * (1.f / 96.f) + EPSF);
                    sm[OFF_RH + col + 1] = rp;                 // own next-step RH
                    rsl[(t % DD) * NCOL + n0 + col] = rp;      // publish
                }
            }
        }
        __syncthreads();

        // ---- Phase E: v = s*RO*onw -> smem HP interior + global ring + out ----
        float* hdst = hbl + (t % DD) * SLOT;
        for (int idx = tid; idx < CCH * WW; idx += NT) {
            int cc = idx / WW, m = idx - cc * WW;
            if (m < M) {
                float v = sm[OFF_HC + idx] * sm[OFF_RO + m] * sm[OFF_ONW + cc];
                int n = n0 + m;
                hdst[cc * NCOL + n] = v;
                sm[OFF_HP + cc * WH + m + 1] = v;   // next step's interior hp
                if (l == LL - 1)
                    out[(((n >> 6) * CCH + cc) * TT + t) * FF + (n & 63)] = v;
            }
        }
        __threadfence();       // publish ring + stats gpu-wide
        __syncthreads();
        if (tid == 0) st_vol(&g_prog[l * PP + part], t + 1);
    }
}

// ---------------------------------------------------------------------------
extern "C" void kernel_launch(void* const* d_in, const int* in_sizes, int n_in,
                              void* d_out, int out_size) {
    const float* x    = (const float*)d_in[0];
    const float* inw  = (const float*)d_in[1];
    const float* hnw  = (const float*)d_in[2];
    const float* xpw  = (const float*)d_in[3];
    const float* xpb  = (const float*)d_in[4];
    const float* hmw  = (const float*)d_in[5];
    const float* hmb  = (const float*)d_in[6];
    const float* hpw  = (const float*)d_in[7];
    const float* hpb  = (const float*)d_in[8];
    const float* onw  = (const float*)d_in[9];
    float* out = (float*)d_out;

    cudaFuncSetAttribute(gru_main, cudaFuncAttributeMaxDynamicSharedMemorySize, SMEM_BYTES);

    gru_init<<<256, 256>>>(xpw, hpw, inw, hnw, hmb, hpb);
    gru_main<<<LL * PP, NT, SMEM_BYTES>>>(x, xpb, hmw, onw, out);
}